// round 10
// baseline (speedup 1.0000x reference)
#include <cuda_runtime.h>
#include <cuda_fp16.h>

#define NPIX  65536   // 256*256
#define NT    1024
#define KS    8       // Lloyd scan: uint4 (8 x f16 px) groups per thread

#define SR_OFF   131072               // u8 sr image (64KB)
#define SCR_OFF  196608
#define SMEM_TOTAL (SCR_OFF + 2048)

__device__ double   g_partials[1024];
__device__ unsigned g_count = 0;

struct Scratch {
    float    fmin[32], fmax[32], fsum[32], fsq[32];
    unsigned usq[32];
    float    nred[32], sred[32];
    unsigned nmw[32], sqw[32];
    int      hq[24];                  // threshold-bits history (iter 0..20)
    int      qt, done, flip;
    unsigned border[4];
    float    sumsq_tot;
    unsigned sq8_tot;
};

extern "C" __global__ void __launch_bounds__(NT, 1)
mask_loss_main(const float* __restrict__ hr, const float* __restrict__ sr,
               float* __restrict__ out, int B)
{
    extern __shared__ unsigned char smem[];
    unsigned short* qs   = (unsigned short*)smem;   // half bits (positive => bit order = value order)
    uint4*          q128 = (uint4*)smem;            // 8 px (4 x half2) per uint4
    uint2*          sr2  = (uint2*)(smem + SR_OFF); // 8 sr bytes per uint2
    Scratch* sc = (Scratch*)(smem + SCR_OFF);

    const int tid  = threadIdx.x;
    const int lane = tid & 31;
    const int warp = tid >> 5;
    const int b    = blockIdx.x;

    if (tid < 4) sc->border[tid] = 0;

    // ---------------- Phase 1: single streaming pass over hr (3 planes) + sr ----------------
    const float4* p0 = (const float4*)(hr + (size_t)b * 3 * NPIX);
    const float4* p1 = p0 + NPIX / 4;
    const float4* p2 = p1 + NPIX / 4;
    const float4* ps = (const float4*)(sr + (size_t)b * NPIX);

    float gmin = 3.0e38f, gmax = -3.0e38f;
    float ssum = 0.0f, sumsq = 0.0f;
    unsigned sq8 = 0;
    const float inv3 = 1.0f / 3.0f;

    #pragma unroll
    for (int k = 0; k < 8; k++) {
        const int g0 = k * 2048 + 2 * tid;   // two adjacent float4 groups
        float4 a0 = p0[g0],     c0 = p1[g0],     d0 = p2[g0];
        float4 a1 = p0[g0 + 1], c1 = p1[g0 + 1], d1 = p2[g0 + 1];
        float4 s0 = ps[g0],     s1 = ps[g0 + 1];

        float x0 = (a0.x + c0.x + d0.x) * inv3;
        float x1 = (a0.y + c0.y + d0.y) * inv3;
        float x2 = (a0.z + c0.z + d0.z) * inv3;
        float x3 = (a0.w + c0.w + d0.w) * inv3;
        float x4 = (a1.x + c1.x + d1.x) * inv3;
        float x5 = (a1.y + c1.y + d1.y) * inv3;
        float x6 = (a1.z + c1.z + d1.z) * inv3;
        float x7 = (a1.w + c1.w + d1.w) * inv3;

        gmin = fminf(gmin, fminf(fminf(fminf(x0, x1), fminf(x2, x3)),
                                 fminf(fminf(x4, x5), fminf(x6, x7))));
        gmax = fmaxf(gmax, fmaxf(fmaxf(fmaxf(x0, x1), fmaxf(x2, x3)),
                                 fmaxf(fmaxf(x4, x5), fmaxf(x6, x7))));
        ssum += ((x0 + x1) + (x2 + x3)) + ((x4 + x5) + (x6 + x7));

        __half2 h0 = __floats2half2_rn(x0, x1);
        __half2 h1 = __floats2half2_rn(x2, x3);
        __half2 h2 = __floats2half2_rn(x4, x5);
        __half2 h3 = __floats2half2_rn(x6, x7);
        uint4 pk;
        pk.x = *(unsigned*)&h0;
        pk.y = *(unsigned*)&h1;
        pk.z = *(unsigned*)&h2;
        pk.w = *(unsigned*)&h3;
        q128[k * 1024 + tid] = pk;

        sumsq += s0.x*s0.x + s0.y*s0.y + s0.z*s0.z + s0.w*s0.w;
        sumsq += s1.x*s1.x + s1.y*s1.y + s1.z*s1.z + s1.w*s1.w;

        unsigned b0 = min((unsigned)(s0.x * 256.0f), 255u);
        unsigned b1 = min((unsigned)(s0.y * 256.0f), 255u);
        unsigned b2 = min((unsigned)(s0.z * 256.0f), 255u);
        unsigned b3 = min((unsigned)(s0.w * 256.0f), 255u);
        unsigned b4 = min((unsigned)(s1.x * 256.0f), 255u);
        unsigned b5 = min((unsigned)(s1.y * 256.0f), 255u);
        unsigned b6 = min((unsigned)(s1.z * 256.0f), 255u);
        unsigned b7 = min((unsigned)(s1.w * 256.0f), 255u);
        sq8 += b0 + b1 + b2 + b3 + b4 + b5 + b6 + b7;

        uint2 pb;
        pb.x = b0 | (b1 << 8) | (b2 << 16) | (b3 << 24);
        pb.y = b4 | (b5 << 8) | (b6 << 16) | (b7 << 24);
        sr2[k * 1024 + tid] = pb;
    }

    #pragma unroll
    for (int o = 16; o; o >>= 1) {
        gmin = fminf(gmin, __shfl_xor_sync(~0u, gmin, o));
        gmax = fmaxf(gmax, __shfl_xor_sync(~0u, gmax, o));
        ssum  += __shfl_xor_sync(~0u, ssum, o);
        sumsq += __shfl_xor_sync(~0u, sumsq, o);
        sq8   += __shfl_xor_sync(~0u, sq8, o);
    }
    if (lane == 0) {
        sc->fmin[warp] = gmin; sc->fmax[warp] = gmax;
        sc->fsum[warp] = ssum; sc->fsq[warp] = sumsq; sc->usq[warp] = sq8;
    }
    __syncthreads();

    float Stot = 0.0f;   // valid only in (warp 0, lane 0)
    if (warp == 0) {
        float mn = sc->fmin[lane];
        float mx = sc->fmax[lane];
        float s  = sc->fsum[lane];
        float fq = sc->fsq[lane];
        unsigned uq = sc->usq[lane];
        #pragma unroll
        for (int o = 16; o; o >>= 1) {
            mn = fminf(mn, __shfl_xor_sync(~0u, mn, o));
            mx = fmaxf(mx, __shfl_xor_sync(~0u, mx, o));
            s  += __shfl_xor_sync(~0u, s, o);
            fq += __shfl_xor_sync(~0u, fq, o);
            uq += __shfl_xor_sync(~0u, uq, o);
        }
        if (lane == 0) {
            Stot = s;
            sc->sumsq_tot = fq;
            sc->sq8_tot   = uq;
            float t = 0.5f * (mn + mx);                 // init c0=min, c1=max
            int qb = (int)__half_as_ushort(__float2half_rn(t));
            sc->qt = qb;
            sc->hq[0] = qb;
            sc->done = 0;
        }
    }
    __syncthreads();

    // ---------------- Phase 2: Lloyd iterations (f16x2 scan + full-history exit) ----------------
    int qt = sc->qt;

    for (int it = 0; it < 20; it++) {
        const __half2 t2 = __half2half2(__ushort_as_half((unsigned short)qt));
        __half2 n2 = __floats2half2_rn(0.0f, 0.0f);
        __half2 s2 = n2;

        #pragma unroll
        for (int k = 0; k < KS; k++) {
            uint4 v = q128[tid + k * NT];
            __half2 a0 = *(__half2*)&v.x;
            __half2 a1 = *(__half2*)&v.y;
            __half2 a2 = *(__half2*)&v.z;
            __half2 a3 = *(__half2*)&v.w;
            __half2 m0 = __hgt2(a0, t2);
            __half2 m1 = __hgt2(a1, t2);
            __half2 m2 = __hgt2(a2, t2);
            __half2 m3 = __hgt2(a3, t2);
            n2 = __hadd2(n2, __hadd2(__hadd2(m0, m1), __hadd2(m2, m3)));
            s2 = __hfma2(m0, a0, s2);
            s2 = __hfma2(m1, a1, s2);
            s2 = __hfma2(m2, a2, s2);
            s2 = __hfma2(m3, a3, s2);
        }

        float n = __low2float(n2) + __high2float(n2);   // counts <= 32/half: exact
        float s = __low2float(s2) + __high2float(s2);
        #pragma unroll
        for (int o = 16; o; o >>= 1) {
            n += __shfl_xor_sync(~0u, n, o);
            s += __shfl_xor_sync(~0u, s, o);
        }
        if (lane == 0) { sc->nred[warp] = n; sc->sred[warp] = s; }
        __syncthreads();

        if (warp == 0) {
            float N1f = sc->nred[lane];
            float S1  = sc->sred[lane];
            #pragma unroll
            for (int o = 16; o; o >>= 1) {
                N1f += __shfl_xor_sync(~0u, N1f, o);
                S1  += __shfl_xor_sync(~0u, S1, o);
            }
            if (lane == 0) {
                int N1 = (int)rintf(N1f);
                int N0 = NPIX - N1;
                float s0 = Stot - S1;
                float c1 = S1 / (float)max(N1, 1);
                float c0 = s0 / (float)max(N0, 1);
                float t  = 0.5f * (c0 + c1);
                int qb = (int)__half_as_ushort(__float2half_rn(t));

                int fin = -1;
                #pragma unroll
                for (int j = 0; j < 21; j++) {
                    if (j <= it && fin < 0 && sc->hq[j] == qb) {
                        int L   = it + 1 - j;          // cycle length
                        int idx = j + ((20 - j) % L);  // index of qt_20 within cycle
                        fin = sc->hq[idx];
                    }
                }
                if (fin >= 0) { sc->qt = fin; sc->done = 1; }
                else          { sc->hq[it + 1] = qb; sc->qt = qb; }
            }
        }
        __syncthreads();
        qt = sc->qt;
        if (sc->done) break;
    }

    // ---------------- Phase 3a: border vote (bit compare on positive halves) ----------------
    {
        const int g = tid >> 8;          // 0:row0 1:row255 2:col0 3:col255 (warp-uniform)
        const int j = tid & 255;
        int qv;
        if      (g == 0) qv = (int)qs[j];
        else if (g == 1) qv = (int)qs[65280 + j];
        else if (g == 2) qv = (int)qs[j << 8];
        else             qv = (int)qs[(j << 8) + 255];
        unsigned c = (qv > qt) ? 1u : 0u;
        #pragma unroll
        for (int o = 16; o; o >>= 1) c += __shfl_xor_sync(~0u, c, o);
        if (lane == 0) atomicAdd(&sc->border[g], c);
    }
    __syncthreads();
    if (tid == 0) {
        int num = (sc->border[0] > 128u) + (sc->border[1] > 128u)
                + (sc->border[2] > 128u) + (sc->border[3] > 128u);
        sc->flip = (num >= 3) ? 1 : 0;
    }

    // ---------------- Phase 3b: masked count + sr8 sum (pure SMEM) ----------------
    unsigned nm = 0, sq = 0;
    #pragma unroll
    for (int k = 0; k < 8; k++) {
        uint4 v  = q128[tid + k * NT];
        uint2 s8 = sr2[tid + k * NT];
        int q0 = (int)(v.x & 0xFFFFu), q1 = (int)(v.x >> 16);
        int q2 = (int)(v.y & 0xFFFFu), q3 = (int)(v.y >> 16);
        int q4 = (int)(v.z & 0xFFFFu), q5 = (int)(v.z >> 16);
        int q6 = (int)(v.w & 0xFFFFu), q7 = (int)(v.w >> 16);
        unsigned b0 = s8.x & 255u,        b1 = (s8.x >> 8) & 255u;
        unsigned b2 = (s8.x >> 16) & 255u, b3 = s8.x >> 24;
        unsigned b4 = s8.y & 255u,        b5 = (s8.y >> 8) & 255u;
        unsigned b6 = (s8.y >> 16) & 255u, b7 = s8.y >> 24;
        if (q0 > qt) { nm++; sq += b0; }
        if (q1 > qt) { nm++; sq += b1; }
        if (q2 > qt) { nm++; sq += b2; }
        if (q3 > qt) { nm++; sq += b3; }
        if (q4 > qt) { nm++; sq += b4; }
        if (q5 > qt) { nm++; sq += b5; }
        if (q6 > qt) { nm++; sq += b6; }
        if (q7 > qt) { nm++; sq += b7; }
    }
    #pragma unroll
    for (int o = 16; o; o >>= 1) {
        nm += __shfl_xor_sync(~0u, nm, o);
        sq += __shfl_xor_sync(~0u, sq, o);
    }
    if (lane == 0) { sc->nmw[warp] = nm; sc->sqw[warp] = sq; }
    __syncthreads();

    // ---------------- Phase 4: per-CTA loss + last-CTA finalize ----------------
    if (warp == 0) {
        unsigned n = sc->nmw[lane], s = sc->sqw[lane];
        #pragma unroll
        for (int o = 16; o; o >>= 1) {
            n += __shfl_xor_sync(~0u, n, o);
            s += __shfl_xor_sync(~0u, s, o);
        }
        if (lane == 0) {
            unsigned Nm = n, Sq = s;
            if (sc->flip) { Nm = 65536u - Nm; Sq = sc->sq8_tot - Sq; }
            float Ssr  = ((float)Sq + 0.5f * (float)Nm) * (1.0f / 256.0f);
            float loss = sc->sumsq_tot - 2.0f * Ssr + (float)Nm;
            g_partials[b] = (double)loss;
        }

        unsigned old = 0;
        if (lane == 0) {
            __threadfence();
            old = atomicAdd(&g_count, 1u);
        }
        old = __shfl_sync(~0u, old, 0);

        if (old == (unsigned)(B - 1)) {          // last CTA: finalize
            __threadfence();
            volatile double* vp = g_partials;
            double tt = 0.0;
            for (int i = lane; i < B; i += 32) tt += vp[i];
            #pragma unroll
            for (int o = 16; o; o >>= 1) tt += __shfl_xor_sync(~0u, tt, o);
            if (lane == 0) {
                out[0] = (float)(tt / ((double)B * (double)NPIX));
                g_count = 0;                     // reset for next graph replay
            }
        }
    }
}

extern "C" void kernel_launch(void* const* d_in, const int* in_sizes, int n_in,
                              void* d_out, int out_size)
{
    const float* hr = (const float*)d_in[0];
    const float* sr = (const float*)d_in[1];
    int B = in_sizes[1] / NPIX;

    cudaFuncSetAttribute(mask_loss_main,
                         cudaFuncAttributeMaxDynamicSharedMemorySize, SMEM_TOTAL);

    mask_loss_main<<<B, NT, SMEM_TOTAL>>>(hr, sr, (float*)d_out, B);
}

// round 11
// speedup vs baseline: 1.0056x; 1.0056x over previous
#include <cuda_runtime.h>
#include <cuda_fp16.h>

#define NPIX  65536   // 256*256
#define NT    1024
#define KS    8       // Lloyd scan: uint4 (8 x f16 px) groups per thread

#define SR_OFF   131072               // u8 sr image (64KB)
#define SCR_OFF  196608
#define SMEM_TOTAL (SCR_OFF + 2048)

__device__ double   g_partials[1024];
__device__ unsigned g_count = 0;

struct Scratch {
    float    fmin[32], fmax[32], fsum[32], fsq[32];
    unsigned usq[32];
    float    nred[32], sred[32];
    unsigned nmw[32], sqw[32];
    int      hq[24];                  // threshold-bits history (iter 0..20)
    int      qt, done, flip;
    unsigned border[4];
    float    sumsq_tot;
    unsigned sq8_tot;
};

extern "C" __global__ void __launch_bounds__(NT, 1)
mask_loss_main(const float* __restrict__ hr, const float* __restrict__ sr,
               float* __restrict__ out, int B)
{
    extern __shared__ unsigned char smem[];
    unsigned short* qs   = (unsigned short*)smem;   // half bits (positive => bit order = value order)
    uint4*          q128 = (uint4*)smem;            // 8 px (4 x half2) per uint4
    uint2*          sr2  = (uint2*)(smem + SR_OFF); // 8 sr bytes per uint2
    Scratch* sc = (Scratch*)(smem + SCR_OFF);

    const int tid  = threadIdx.x;
    const int lane = tid & 31;
    const int warp = tid >> 5;
    const int b    = blockIdx.x;

    if (tid < 4) sc->border[tid] = 0;

    // ---------------- Phase 1: single streaming pass over hr (3 planes) + sr ----------------
    const float4* p0 = (const float4*)(hr + (size_t)b * 3 * NPIX);
    const float4* p1 = p0 + NPIX / 4;
    const float4* p2 = p1 + NPIX / 4;
    const float4* ps = (const float4*)(sr + (size_t)b * NPIX);

    float gmin = 3.0e38f, gmax = -3.0e38f;
    float ssum = 0.0f, sumsq = 0.0f;
    unsigned sq8 = 0;
    const float inv3 = 1.0f / 3.0f;

    #pragma unroll
    for (int k = 0; k < 8; k++) {
        const int g0 = k * 2048 + 2 * tid;   // two adjacent float4 groups
        float4 a0 = p0[g0],     c0 = p1[g0],     d0 = p2[g0];
        float4 a1 = p0[g0 + 1], c1 = p1[g0 + 1], d1 = p2[g0 + 1];
        float4 s0 = ps[g0],     s1 = ps[g0 + 1];

        float x0 = (a0.x + c0.x + d0.x) * inv3;
        float x1 = (a0.y + c0.y + d0.y) * inv3;
        float x2 = (a0.z + c0.z + d0.z) * inv3;
        float x3 = (a0.w + c0.w + d0.w) * inv3;
        float x4 = (a1.x + c1.x + d1.x) * inv3;
        float x5 = (a1.y + c1.y + d1.y) * inv3;
        float x6 = (a1.z + c1.z + d1.z) * inv3;
        float x7 = (a1.w + c1.w + d1.w) * inv3;

        gmin = fminf(gmin, fminf(fminf(fminf(x0, x1), fminf(x2, x3)),
                                 fminf(fminf(x4, x5), fminf(x6, x7))));
        gmax = fmaxf(gmax, fmaxf(fmaxf(fmaxf(x0, x1), fmaxf(x2, x3)),
                                 fmaxf(fmaxf(x4, x5), fmaxf(x6, x7))));
        ssum += ((x0 + x1) + (x2 + x3)) + ((x4 + x5) + (x6 + x7));

        __half2 h0 = __floats2half2_rn(x0, x1);
        __half2 h1 = __floats2half2_rn(x2, x3);
        __half2 h2 = __floats2half2_rn(x4, x5);
        __half2 h3 = __floats2half2_rn(x6, x7);
        uint4 pk;
        pk.x = *(unsigned*)&h0;
        pk.y = *(unsigned*)&h1;
        pk.z = *(unsigned*)&h2;
        pk.w = *(unsigned*)&h3;
        q128[k * 1024 + tid] = pk;

        sumsq += s0.x*s0.x + s0.y*s0.y + s0.z*s0.z + s0.w*s0.w;
        sumsq += s1.x*s1.x + s1.y*s1.y + s1.z*s1.z + s1.w*s1.w;

        unsigned b0 = min((unsigned)(s0.x * 256.0f), 255u);
        unsigned b1 = min((unsigned)(s0.y * 256.0f), 255u);
        unsigned b2 = min((unsigned)(s0.z * 256.0f), 255u);
        unsigned b3 = min((unsigned)(s0.w * 256.0f), 255u);
        unsigned b4 = min((unsigned)(s1.x * 256.0f), 255u);
        unsigned b5 = min((unsigned)(s1.y * 256.0f), 255u);
        unsigned b6 = min((unsigned)(s1.z * 256.0f), 255u);
        unsigned b7 = min((unsigned)(s1.w * 256.0f), 255u);
        sq8 += b0 + b1 + b2 + b3 + b4 + b5 + b6 + b7;

        uint2 pb;
        pb.x = b0 | (b1 << 8) | (b2 << 16) | (b3 << 24);
        pb.y = b4 | (b5 << 8) | (b6 << 16) | (b7 << 24);
        sr2[k * 1024 + tid] = pb;
    }

    #pragma unroll
    for (int o = 16; o; o >>= 1) {
        gmin = fminf(gmin, __shfl_xor_sync(~0u, gmin, o));
        gmax = fmaxf(gmax, __shfl_xor_sync(~0u, gmax, o));
        ssum  += __shfl_xor_sync(~0u, ssum, o);
        sumsq += __shfl_xor_sync(~0u, sumsq, o);
        sq8   += __shfl_xor_sync(~0u, sq8, o);
    }
    if (lane == 0) {
        sc->fmin[warp] = gmin; sc->fmax[warp] = gmax;
        sc->fsum[warp] = ssum; sc->fsq[warp] = sumsq; sc->usq[warp] = sq8;
    }
    __syncthreads();

    float Stot = 0.0f;   // valid only in (warp 0, lane 0)
    if (warp == 0) {
        float mn = sc->fmin[lane];
        float mx = sc->fmax[lane];
        float s  = sc->fsum[lane];
        float fq = sc->fsq[lane];
        unsigned uq = sc->usq[lane];
        #pragma unroll
        for (int o = 16; o; o >>= 1) {
            mn = fminf(mn, __shfl_xor_sync(~0u, mn, o));
            mx = fmaxf(mx, __shfl_xor_sync(~0u, mx, o));
            s  += __shfl_xor_sync(~0u, s, o);
            fq += __shfl_xor_sync(~0u, fq, o);
            uq += __shfl_xor_sync(~0u, uq, o);
        }
        if (lane == 0) {
            Stot = s;
            sc->sumsq_tot = fq;
            sc->sq8_tot   = uq;
            float t = 0.5f * (mn + mx);                 // init c0=min, c1=max
            int qb = (int)__half_as_ushort(__float2half_rn(t));
            sc->qt = qb;
            sc->hq[0] = qb;
            sc->done = 0;
        }
    }
    __syncthreads();

    // ---------------- Phase 2: Lloyd iterations (f16x2 scan + full-history exit) ----------------
    int qt = sc->qt;

    for (int it = 0; it < 20; it++) {
        const __half2 t2 = __half2half2(__ushort_as_half((unsigned short)qt));
        __half2 n2 = __floats2half2_rn(0.0f, 0.0f);
        __half2 s2 = n2;

        #pragma unroll
        for (int k = 0; k < KS; k++) {
            uint4 v = q128[tid + k * NT];
            __half2 a0 = *(__half2*)&v.x;
            __half2 a1 = *(__half2*)&v.y;
            __half2 a2 = *(__half2*)&v.z;
            __half2 a3 = *(__half2*)&v.w;
            __half2 m0 = __hgt2(a0, t2);
            __half2 m1 = __hgt2(a1, t2);
            __half2 m2 = __hgt2(a2, t2);
            __half2 m3 = __hgt2(a3, t2);
            n2 = __hadd2(n2, __hadd2(__hadd2(m0, m1), __hadd2(m2, m3)));
            s2 = __hfma2(m0, a0, s2);
            s2 = __hfma2(m1, a1, s2);
            s2 = __hfma2(m2, a2, s2);
            s2 = __hfma2(m3, a3, s2);
        }

        float n = __low2float(n2) + __high2float(n2);   // counts <= 32/half: exact
        float s = __low2float(s2) + __high2float(s2);
        #pragma unroll
        for (int o = 16; o; o >>= 1) {
            n += __shfl_xor_sync(~0u, n, o);
            s += __shfl_xor_sync(~0u, s, o);
        }
        if (lane == 0) { sc->nred[warp] = n; sc->sred[warp] = s; }
        __syncthreads();

        if (warp == 0) {
            float N1f = sc->nred[lane];
            float S1  = sc->sred[lane];
            #pragma unroll
            for (int o = 16; o; o >>= 1) {
                N1f += __shfl_xor_sync(~0u, N1f, o);
                S1  += __shfl_xor_sync(~0u, S1, o);
            }
            if (lane == 0) {
                int N1 = (int)rintf(N1f);
                int N0 = NPIX - N1;
                float s0 = Stot - S1;
                float c1 = S1 / (float)max(N1, 1);
                float c0 = s0 / (float)max(N0, 1);
                float t  = 0.5f * (c0 + c1);
                int qb = (int)__half_as_ushort(__float2half_rn(t));

                int fin = -1;
                #pragma unroll
                for (int j = 0; j < 21; j++) {
                    if (j <= it && fin < 0 && sc->hq[j] == qb) {
                        int L   = it + 1 - j;          // cycle length
                        int idx = j + ((20 - j) % L);  // index of qt_20 within cycle
                        fin = sc->hq[idx];
                    }
                }
                if (fin >= 0) { sc->qt = fin; sc->done = 1; }
                else          { sc->hq[it + 1] = qb; sc->qt = qb; }
            }
        }
        __syncthreads();
        qt = sc->qt;
        if (sc->done) break;
    }

    // ---------------- Phase 3a: border vote (bit compare on positive halves) ----------------
    {
        const int g = tid >> 8;          // 0:row0 1:row255 2:col0 3:col255 (warp-uniform)
        const int j = tid & 255;
        int qv;
        if      (g == 0) qv = (int)qs[j];
        else if (g == 1) qv = (int)qs[65280 + j];
        else if (g == 2) qv = (int)qs[j << 8];
        else             qv = (int)qs[(j << 8) + 255];
        unsigned c = (qv > qt) ? 1u : 0u;
        #pragma unroll
        for (int o = 16; o; o >>= 1) c += __shfl_xor_sync(~0u, c, o);
        if (lane == 0) atomicAdd(&sc->border[g], c);
    }
    __syncthreads();
    if (tid == 0) {
        int num = (sc->border[0] > 128u) + (sc->border[1] > 128u)
                + (sc->border[2] > 128u) + (sc->border[3] > 128u);
        sc->flip = (num >= 3) ? 1 : 0;
    }

    // ---------------- Phase 3b: masked count + sr8 sum (pure SMEM) ----------------
    unsigned nm = 0, sq = 0;
    #pragma unroll
    for (int k = 0; k < 8; k++) {
        uint4 v  = q128[tid + k * NT];
        uint2 s8 = sr2[tid + k * NT];
        int q0 = (int)(v.x & 0xFFFFu), q1 = (int)(v.x >> 16);
        int q2 = (int)(v.y & 0xFFFFu), q3 = (int)(v.y >> 16);
        int q4 = (int)(v.z & 0xFFFFu), q5 = (int)(v.z >> 16);
        int q6 = (int)(v.w & 0xFFFFu), q7 = (int)(v.w >> 16);
        unsigned b0 = s8.x & 255u,        b1 = (s8.x >> 8) & 255u;
        unsigned b2 = (s8.x >> 16) & 255u, b3 = s8.x >> 24;
        unsigned b4 = s8.y & 255u,        b5 = (s8.y >> 8) & 255u;
        unsigned b6 = (s8.y >> 16) & 255u, b7 = s8.y >> 24;
        if (q0 > qt) { nm++; sq += b0; }
        if (q1 > qt) { nm++; sq += b1; }
        if (q2 > qt) { nm++; sq += b2; }
        if (q3 > qt) { nm++; sq += b3; }
        if (q4 > qt) { nm++; sq += b4; }
        if (q5 > qt) { nm++; sq += b5; }
        if (q6 > qt) { nm++; sq += b6; }
        if (q7 > qt) { nm++; sq += b7; }
    }
    #pragma unroll
    for (int o = 16; o; o >>= 1) {
        nm += __shfl_xor_sync(~0u, nm, o);
        sq += __shfl_xor_sync(~0u, sq, o);
    }
    if (lane == 0) { sc->nmw[warp] = nm; sc->sqw[warp] = sq; }
    __syncthreads();

    // ---------------- Phase 4: per-CTA loss + last-CTA finalize ----------------
    if (warp == 0) {
        unsigned n = sc->nmw[lane], s = sc->sqw[lane];
        #pragma unroll
        for (int o = 16; o; o >>= 1) {
            n += __shfl_xor_sync(~0u, n, o);
            s += __shfl_xor_sync(~0u, s, o);
        }
        if (lane == 0) {
            unsigned Nm = n, Sq = s;
            if (sc->flip) { Nm = 65536u - Nm; Sq = sc->sq8_tot - Sq; }
            float Ssr  = ((float)Sq + 0.5f * (float)Nm) * (1.0f / 256.0f);
            float loss = sc->sumsq_tot - 2.0f * Ssr + (float)Nm;
            g_partials[b] = (double)loss;
        }

        unsigned old = 0;
        if (lane == 0) {
            __threadfence();
            old = atomicAdd(&g_count, 1u);
        }
        old = __shfl_sync(~0u, old, 0);

        if (old == (unsigned)(B - 1)) {          // last CTA: finalize
            __threadfence();
            volatile double* vp = g_partials;
            double tt = 0.0;
            for (int i = lane; i < B; i += 32) tt += vp[i];
            #pragma unroll
            for (int o = 16; o; o >>= 1) tt += __shfl_xor_sync(~0u, tt, o);
            if (lane == 0) {
                out[0] = (float)(tt / ((double)B * (double)NPIX));
                g_count = 0;                     // reset for next graph replay
            }
        }
    }
}

extern "C" void kernel_launch(void* const* d_in, const int* in_sizes, int n_in,
                              void* d_out, int out_size)
{
    const float* hr = (const float*)d_in[0];
    const float* sr = (const float*)d_in[1];
    int B = in_sizes[1] / NPIX;

    cudaFuncSetAttribute(mask_loss_main,
                         cudaFuncAttributeMaxDynamicSharedMemorySize, SMEM_TOTAL);

    mask_loss_main<<<B, NT, SMEM_TOTAL>>>(hr, sr, (float*)d_out, B);
}